// round 17
// baseline (speedup 1.0000x reference)
#include <cuda_runtime.h>
#include <cuda_fp16.h>
#include <stdint.h>

// Problem constants
#define B_ 1024
#define I_ 256
#define O_ 256
#define K_ 128

#define NSEG 8          // i-segments: grid = 32 b-tiles x 8 = 256 CTAs (0.86 wave at occ 2)
#define ISEG (I_ / NSEG)
#define BTILE 32        // batches per CTA
#define KSPLIT 4        // prepack k-parallelism / prep b-slice
#define ROWBYTES (O_ * 4)   // 1024 B per k-row of g_pre

// Per-(b,i) packed activation [i][b], 8 bytes: {half2(silu, frac), l*1024 byte offset}
__device__ uint2 g_pk8[I_ * B_];
// Packed spline pairs [i][k][o] = half2(c[o,i,k]*s, c[o,i,k+1]*s)  (33.5 MB, L2-resident)
__device__ unsigned int g_pre[(size_t)I_ * K_ * O_];
// Transposed base weights [i][o]
__device__ float g_bwT[I_ * O_];
// Exclusive partial sums per i-segment
__device__ float g_part[NSEG][B_][O_];
// Arrival counters per b-tile (reset by the reducing CTA)
__device__ int g_cnt[B_ / BTILE];

__device__ __forceinline__ unsigned int h2bits(__half2 h) {
    return *reinterpret_cast<unsigned int*>(&h);
}
__device__ __forceinline__ float2 bits2f2(unsigned int u) {
    return __half22float2(*reinterpret_cast<__half2*>(&u));
}

// Fused preprocessing: activation prep + coefficient prepack + bw transpose.
__global__ __launch_bounds__(256) void prepack_kernel(
    const float* __restrict__ x,      // [B, I]
    const float* __restrict__ coeff,  // [O, I, K]
    const float* __restrict__ scale,  // [O, I]
    const float* __restrict__ bw)     // [O, I]
{
    const int i = blockIdx.x;
    const int y = blockIdx.y;
    const int o = threadIdx.x;

    // ---- prep slice: b = y*256 + o ----
    {
        const int b = y * 256 + o;
        float xv = __ldg(&x[b * I_ + i]);
        float ax = fabsf(xv);
        float e  = __expf(-2.0f * ax);
        float r  = (1.0f - e) / (1.0f + e);
        float p  = copysignf(r, xv);              // tanh(x) in [-1,1] => clip identity
        float sg = 1.0f / (1.0f + __expf(-p));
        float act = p * sg;                        // silu(p)
        float scaled = fminf(fmaxf((p + 1.0f) * 63.5f, 0.0f), 127.0f);
        int   l    = (int)scaled;
        float frac = scaled - (float)l;
        uint2 v;
        v.x = h2bits(__floats2half2_rn(act, frac));
        v.y = (unsigned int)(l * ROWBYTES);
        g_pk8[i * B_ + b] = v;
    }

    // ---- prepack slice: k-chunk [y*32, y*32+32) for output o ----
    const int kb = y * (K_ / KSPLIT);
    const float* src = coeff + ((size_t)o * I_ + i) * (size_t)K_;
    float s = __ldg(&scale[o * I_ + i]);
    unsigned int* dst = g_pre + (size_t)i * (K_ * O_) + (size_t)kb * O_ + o;

    float c[33];
    const float4* s4 = (const float4*)(src + kb);
#pragma unroll
    for (int j = 0; j < 8; j++) {
        float4 v = s4[j];
        c[4 * j] = v.x; c[4 * j + 1] = v.y; c[4 * j + 2] = v.z; c[4 * j + 3] = v.w;
    }
    // Right-tap of the chunk's last k: next element, or wrap (only read at l=127 where frac=0)
    c[32] = (kb + 32 < K_) ? __ldg(src + kb + 32) : __ldg(src);

#pragma unroll
    for (int k = 0; k < 32; k++)
        dst[(size_t)k * O_] = h2bits(__floats2half2_rn(c[k] * s, c[k + 1] * s));

    if (y == 0)
        g_bwT[i * O_ + o] = __ldg(&bw[o * I_ + i]);   // coalesced write
}

// Consume one batch: 4 outputs' packed pairs + activation -> acc row.
__device__ __forceinline__ void consume(unsigned int pkbits, uint4 ge,
                                        float4 wv, float (&acc)[4]) {
    float2 af = bits2f2(pkbits);       // (silu, frac)
    float omf = 1.0f - af.y;
    float2 c0 = bits2f2(ge.x);
    float2 c1 = bits2f2(ge.y);
    float2 c2 = bits2f2(ge.z);
    float2 c3 = bits2f2(ge.w);
    acc[0] = fmaf(omf, c0.x, acc[0]); acc[0] = fmaf(af.y, c0.y, acc[0]); acc[0] = fmaf(af.x, wv.x, acc[0]);
    acc[1] = fmaf(omf, c1.x, acc[1]); acc[1] = fmaf(af.y, c1.y, acc[1]); acc[1] = fmaf(af.x, wv.y, acc[1]);
    acc[2] = fmaf(omf, c2.x, acc[2]); acc[2] = fmaf(af.y, c2.y, acc[2]); acc[2] = fmaf(af.x, wv.z, acc[2]);
    acc[3] = fmaf(omf, c3.x, acc[3]); acc[3] = fmaf(af.y, c3.y, acc[3]); acc[3] = fmaf(af.x, wv.w, acc[3]);
}

// Main: barrier-free, 2-deep gather pipeline. Lane = 4 outputs (LDG.128 gather).
// 512 threads = 16 warps: warp = (o-half 0..1, 128 o's) x (b-eighth 0..7, 4 batches).
__global__ __launch_bounds__(512, 2) void kan_main(
    const float* __restrict__ bias, float* __restrict__ out)
{
    __shared__ __align__(16) uint2 sPk[ISEG * BTILE];   // 8 KB
    __shared__ int sLast;

    const int tid  = threadIdx.x;
    const int lane = tid & 31;
    const int warp = tid >> 5;
    const int oh   = warp & 1;
    const int be   = warp >> 1;
    const int ol   = oh * 128 + 4 * lane;   // this lane's 4 outputs (16B aligned)
    const int b0   = blockIdx.x * BTILE;
    const int ibeg = blockIdx.y * ISEG;

    // Stage pk for the whole segment: 1024 uint2 = 512 uint4, one per thread
    ((uint4*)sPk)[tid] =
        *(const uint4*)(g_pk8 + (ibeg + (tid >> 4)) * B_ + b0 + 2 * (tid & 15));
    __syncthreads();

    float acc[4][4];
#pragma unroll
    for (int j = 0; j < 4; j++) {
        acc[j][0] = 0.0f; acc[j][1] = 0.0f; acc[j][2] = 0.0f; acc[j][3] = 0.0f;
    }

    const char* gb = (const char*)g_pre + ((size_t)ibeg * (K_ * O_) + ol) * 4u;

    // Prologue: pk + gathers for (ii=0, first batch pair)
    uint4 pkA = *(const uint4*)(sPk + be * 4);           // {pk0, pk1}
    uint4 geA0 = *(const uint4*)(gb + pkA.y);
    uint4 geA1 = *(const uint4*)(gb + pkA.w);

    for (int ii = 0; ii < ISEG; ii++) {
        const float4 wv = *(const float4*)(g_bwT + (ibeg + ii) * O_ + ol);

        // Prefetch second batch pair of this i
        uint4 pkB = *(const uint4*)(sPk + ii * BTILE + be * 4 + 2);   // {pk2, pk3}
        uint4 geB0 = *(const uint4*)(gb + pkB.y);
        uint4 geB1 = *(const uint4*)(gb + pkB.w);

        // Consume first pair (gathers issued one half-step ago)
        consume(pkA.x, geA0, wv, acc[0]);
        consume(pkA.z, geA1, wv, acc[1]);

        gb += (size_t)K_ * O_ * 4u;

        // Prefetch first pair of next i
        if (ii + 1 < ISEG) {
            pkA = *(const uint4*)(sPk + (ii + 1) * BTILE + be * 4);
            geA0 = *(const uint4*)(gb + pkA.y);
            geA1 = *(const uint4*)(gb + pkA.w);
        }

        // Consume second pair
        consume(pkB.x, geB0, wv, acc[2]);
        consume(pkB.z, geB1, wv, acc[3]);
    }

    // Exclusive partial slice (contiguous float4 rows)
#pragma unroll
    for (int j = 0; j < 4; j++)
        *(float4*)(&g_part[blockIdx.y][b0 + be * 4 + j][ol]) =
            make_float4(acc[j][0], acc[j][1], acc[j][2], acc[j][3]);

    // Last-arriving CTA of this b-tile reduces the NSEG partials (fixed order, deterministic)
    __threadfence();
    __syncthreads();
    if (tid == 0) {
        int old = atomicAdd(&g_cnt[blockIdx.x], 1);
        sLast = (old == NSEG - 1);
    }
    __syncthreads();
    if (sLast) {
#pragma unroll
        for (int j = 0; j < 4; j++) {
            int t  = tid + 512 * j;          // 2048 float4 = 32 b x 64 f4
            int bl = t >> 6;
            int oq = t & 63;
            float4 s = ((const float4*)&g_part[0][b0 + bl][0])[oq];
#pragma unroll
            for (int sg = 1; sg < NSEG; sg++) {
                float4 v = ((const float4*)&g_part[sg][b0 + bl][0])[oq];
                s.x += v.x; s.y += v.y; s.z += v.z; s.w += v.w;
            }
            float4 bi = ((const float4*)bias)[oq];
            s.x += bi.x; s.y += bi.y; s.z += bi.z; s.w += bi.w;
            ((float4*)&out[(size_t)(b0 + bl) * O_])[oq] = s;
        }
        if (tid == 0) g_cnt[blockIdx.x] = 0;   // re-arm for next replay
    }
}

extern "C" void kernel_launch(void* const* d_in, const int* in_sizes, int n_in,
                              void* d_out, int out_size) {
    const float* x     = (const float*)d_in[0];
    const float* bw    = (const float*)d_in[1];
    const float* coeff = (const float*)d_in[2];
    const float* scale = (const float*)d_in[3];
    const float* bias  = (const float*)d_in[4];
    float* out = (float*)d_out;

    prepack_kernel<<<dim3(I_, KSPLIT), 256>>>(x, coeff, scale, bw);

    dim3 grid(B_ / BTILE, NSEG);   // 32 x 8 = 256 CTAs
    kan_main<<<grid, 512>>>(bias, out);
}